// round 2
// baseline (speedup 1.0000x reference)
#include <cuda_runtime.h>
#include <cuda_bf16.h>
#include <math.h>

// ---------------- problem constants ----------------
#define B_ 2
#define S_ 2048
#define D_ 2048
#define H_ 16
#define RK 512            // KV_RANK
#define ROPE_ 64
#define NOPE_ 128
#define QK_HD 192
#define V_HD 128
#define CD 576            // RK + ROPE (key dim)
#define BS (B_ * S_)      // 4096
#define QROW (H_ * CD)    // 9216  (q_full row stride)
#define QBROW (H_ * QK_HD)// 3072  (q buffer row stride)
#define OLROW (H_ * RK)   // 8192  (o_latent row stride)
#define OVROW (H_ * V_HD) // 2048
#define EPS_ 1.1920929e-07f
#define SCALE_ 0.0721687836487032f   // 192^-0.5

// ---------------- scratch (device globals; no cudaMalloc allowed) ----------------
__device__ float g_q   [(size_t)BS * QBROW];   // (4096, 3072) q projection
__device__ float g_qf  [(size_t)BS * QROW];    // (4096, 16, 576) absorbed+roped q (scaled)
__device__ float g_kvt [(size_t)BS * CD];      // (4096, 576) kv_a projection (pre-norm)
__device__ float g_kf  [(size_t)BS * CD];      // (4096, 576) [rmsnorm latent | roped k_pe]
__device__ float g_ol  [(size_t)BS * OLROW];   // (4096, 16, 512) attention out (latent)
__device__ float g_ov  [(size_t)BS * OVROW];   // (4096, 2048) per-head V-projected out

// ---------------- generic tiled GEMM: C = alpha * A*op(B) (+bias) ----------------
// A: (M,K) row-major, lda.  TB ? B:(N,K) row-major : B:(K,N) row-major.
// Tile: 128(M) x 64(N) x 16(K), 256 threads, 8x4 per thread.
// All M multiples of 128, N of 64, K of 16 in this problem -> no bounds checks.
template<bool TB, bool HASB>
__global__ __launch_bounds__(256)
void gemm_k(int K,
            const float* __restrict__ A, int lda, long aB,
            const float* __restrict__ Bm, int ldb, long bB,
            float* __restrict__ C, int ldc, long cB,
            const float* __restrict__ bias, float alpha)
{
    __shared__ float As[16][132];   // padded, 16B-aligned rows (132*4=528)
    __shared__ float Bs[16][68];    // padded (68*4=272, 16B aligned)

    int z = blockIdx.z;
    A  += (long)z * aB;
    Bm += (long)z * bB;
    C  += (long)z * cB;

    long m0 = (long)blockIdx.y * 128;
    long n0 = (long)blockIdx.x * 64;
    int tid = threadIdx.x;
    int tx = tid & 15, ty = tid >> 4;

    float acc[8][4];
#pragma unroll
    for (int r = 0; r < 8; r++)
#pragma unroll
        for (int c = 0; c < 4; c++) acc[r][c] = 0.f;

    for (int k0 = 0; k0 < K; k0 += 16) {
        {
            int lk = tid & 15, lm = tid >> 4;
#pragma unroll
            for (int i = 0; i < 8; i++)
                As[lk][lm + 16 * i] = A[(m0 + lm + 16 * i) * (long)lda + k0 + lk];
        }
        if (TB) {
            int lk = tid & 15, ln = tid >> 4;
#pragma unroll
            for (int i = 0; i < 4; i++)
                Bs[lk][ln + 16 * i] = Bm[(n0 + ln + 16 * i) * (long)ldb + k0 + lk];
        } else {
            int ln = tid & 63, lk = tid >> 6;
#pragma unroll
            for (int i = 0; i < 4; i++)
                Bs[lk + 4 * i][ln] = Bm[(long)(k0 + lk + 4 * i) * (long)ldb + n0 + ln];
        }
        __syncthreads();

#pragma unroll
        for (int kk = 0; kk < 16; kk++) {
            float4 a0 = *(const float4*)&As[kk][ty * 8];
            float4 a1 = *(const float4*)&As[kk][ty * 8 + 4];
            float4 b0 = *(const float4*)&Bs[kk][tx * 4];
            float av[8] = {a0.x, a0.y, a0.z, a0.w, a1.x, a1.y, a1.z, a1.w};
            float bv[4] = {b0.x, b0.y, b0.z, b0.w};
#pragma unroll
            for (int r = 0; r < 8; r++)
#pragma unroll
                for (int c = 0; c < 4; c++)
                    acc[r][c] = fmaf(av[r], bv[c], acc[r][c]);
        }
        __syncthreads();
    }

#pragma unroll
    for (int r = 0; r < 8; r++) {
        long m = m0 + ty * 8 + r;
        long n = n0 + tx * 4;
        float4 o;
        o.x = acc[r][0] * alpha;
        o.y = acc[r][1] * alpha;
        o.z = acc[r][2] * alpha;
        o.w = acc[r][3] * alpha;
        if (HASB) {
            o.x += bias[n + 0]; o.y += bias[n + 1];
            o.z += bias[n + 2]; o.w += bias[n + 3];
        }
        *(float4*)&C[m * (long)ldc + n] = o;
    }
}

// ---------------- kv post: rmsnorm latent + rope k_pe -> g_kf ----------------
__global__ __launch_bounds__(128)
void kv_post(const float* __restrict__ freqs, const float* __restrict__ knw)
{
    int bs = blockIdx.x;
    int s = bs & (S_ - 1);
    int tid = threadIdx.x;
    const float* row = g_kvt + (long)bs * CD;
    float*       out = g_kf  + (long)bs * CD;

    float ss = 0.f;
    for (int i = tid; i < RK; i += 128) { float v = row[i]; ss += v * v; }
    __shared__ float red[128];
    red[tid] = ss;
    __syncthreads();
    for (int o = 64; o > 0; o >>= 1) {
        if (tid < o) red[tid] += red[tid + o];
        __syncthreads();
    }
    __shared__ float rinv;
    if (tid == 0) rinv = rsqrtf(red[0] * (1.0f / RK) + EPS_);
    __syncthreads();
    float rv = rinv;
    for (int i = tid; i < RK; i += 128) out[i] = row[i] * rv * knw[i];

    if (tid < ROPE_ / 2) {
        float a = row[RK + 2 * tid];
        float b = row[RK + 2 * tid + 1];
        float f = freqs[(long)s * (ROPE_ / 2) + tid];
        float sn, cs;
        sincosf(f, &sn, &cs);
        out[RK + 2 * tid]     = a * cs - b * sn;
        out[RK + 2 * tid + 1] = a * sn + b * cs;
    }
}

// ---------------- q rope: rope q_pe, scale, write to g_qf[..., 512:576] ----------------
__global__ __launch_bounds__(512)
void q_rope(const float* __restrict__ freqs)
{
    int bs = blockIdx.x;
    int s = bs & (S_ - 1);
    int tid = threadIdx.x;           // 512 = 16 heads * 32 pairs
    int h = tid >> 5, i = tid & 31;
    const float* qr = g_q + (long)bs * QBROW + h * QK_HD + NOPE_;
    float a = qr[2 * i], b = qr[2 * i + 1];
    float f = freqs[(long)s * (ROPE_ / 2) + i];
    float sn, cs;
    sincosf(f, &sn, &cs);
    float* o = g_qf + (long)bs * QROW + h * CD + RK;
    o[2 * i]     = (a * cs - b * sn) * SCALE_;
    o[2 * i + 1] = (a * sn + b * cs) * SCALE_;
}

// ---------------- causal flash MQA ----------------
// Per block: 16 queries (one b,h), iterate 32-key tiles up to causal limit.
// K = g_kf row (576); V = first 512 of same row (shared smem tile).
// 128 threads: thread = (qi = tid>>3 in [0,16), g = tid&7 in [0,8)).
// Scores: each thread -> 4 keys {g, g+8, g+16, g+24}. PV: thread owns 16
// interleaved float4 chunks e-chunk index (g + 8c), c in [0,16) -> 64 accum regs.
#define TQ 16
#define TK 32
#define CDP 580  // 576 padded (580*4 % 16 == 0, 580 % 32 == 4 -> conflict-free)

__global__ __launch_bounds__(128)
void flash_attn()
{
    extern __shared__ float smem[];
    float* sq  = smem;                 // TQ * CDP
    float* sk  = sq + TQ * CDP;        // TK * CDP
    float* sS  = sk + TK * CDP;        // TQ * TK
    float* smx = sS + TQ * TK;         // TQ
    float* sl  = smx + TQ;             // TQ
    float* sal = sl + TQ;              // TQ

    int qs = blockIdx.x * TQ;
    int h  = blockIdx.y;
    int b  = blockIdx.z;
    int tid = threadIdx.x;
    int qi = tid >> 3, g = tid & 7;

    // load q tile (scale already folded in)
    const float* qbase = g_qf + ((long)(b * S_ + qs)) * QROW + h * CD;
    for (int idx = tid; idx < TQ * 576; idx += 128) {
        int r = idx / 576, c = idx - r * 576;
        sq[r * CDP + c] = qbase[(long)r * QROW + c];
    }
    if (tid < TQ) { smx[tid] = -3.0e38f; sl[tid] = 0.f; }

    float acc[64];
#pragma unroll
    for (int e = 0; e < 64; e++) acc[e] = 0.f;

    const float* kbase = g_kf + (long)b * S_ * CD;
    int ntk = (qs + TQ - 1) / TK + 1;
    int spos = qs + qi;

    for (int kt = 0; kt < ntk; kt++) {
        int t0 = kt * TK;
        __syncthreads();   // protects sk reuse + first-iter sq/stats init
        for (int idx = tid; idx < TK * 576; idx += 128) {
            int r = idx / 576, c = idx - r * 576;
            sk[r * CDP + c] = kbase[(long)(t0 + r) * CD + c];
        }
        __syncthreads();

        // ---- scores: 4 keys per thread over 576 dims (float4) ----
        const float4* q4 = (const float4*)(sq + qi * CDP);
        const float4* k0 = (const float4*)(sk + (g     ) * CDP);
        const float4* k1 = (const float4*)(sk + (g +  8) * CDP);
        const float4* k2 = (const float4*)(sk + (g + 16) * CDP);
        const float4* k3 = (const float4*)(sk + (g + 24) * CDP);
        float s0 = 0.f, s1 = 0.f, s2 = 0.f, s3 = 0.f;
#pragma unroll 8
        for (int c = 0; c < 144; c++) {
            float4 qv = q4[c];
            float4 a0 = k0[c], a1 = k1[c], a2 = k2[c], a3 = k3[c];
            s0 = fmaf(qv.x, a0.x, fmaf(qv.y, a0.y, fmaf(qv.z, a0.z, fmaf(qv.w, a0.w, s0))));
            s1 = fmaf(qv.x, a1.x, fmaf(qv.y, a1.y, fmaf(qv.z, a1.z, fmaf(qv.w, a1.w, s1))));
            s2 = fmaf(qv.x, a2.x, fmaf(qv.y, a2.y, fmaf(qv.z, a2.z, fmaf(qv.w, a2.w, s2))));
            s3 = fmaf(qv.x, a3.x, fmaf(qv.y, a3.y, fmaf(qv.z, a3.z, fmaf(qv.w, a3.w, s3))));
        }
        sS[qi * TK + g     ] = (t0 + g      <= spos) ? s0 : -3.0e38f;
        sS[qi * TK + g +  8] = (t0 + g +  8 <= spos) ? s1 : -3.0e38f;
        sS[qi * TK + g + 16] = (t0 + g + 16 <= spos) ? s2 : -3.0e38f;
        sS[qi * TK + g + 24] = (t0 + g + 24 <= spos) ? s3 : -3.0e38f;
        __syncthreads();

        // ---- online softmax (one thread per row) ----
        if (tid < TQ) {
            int r = tid;
            float mo = smx[r], mx = mo;
#pragma unroll
            for (int j = 0; j < TK; j++) mx = fmaxf(mx, sS[r * TK + j]);
            float al = __expf(mo - mx);
            float sum = 0.f;
#pragma unroll
            for (int j = 0; j < TK; j++) {
                float p = __expf(sS[r * TK + j] - mx);
                sS[r * TK + j] = p;
                sum += p;
            }
            smx[r] = mx;
            sl[r] = sl[r] * al + sum;
            sal[r] = al;
        }
        __syncthreads();

        // ---- O += P * V  (V = sk[:, :512]); interleaved chunks -> no conflicts ----
        float al = sal[qi];
#pragma unroll
        for (int e = 0; e < 64; e++) acc[e] *= al;
        const float* prow = sS + qi * TK;
        for (int j = 0; j < TK; j++) {
            float p = prow[j];
            const float4* v4 = (const float4*)(sk + j * CDP);
#pragma unroll
            for (int c = 0; c < 16; c++) {
                float4 v = v4[g + 8 * c];
                acc[4 * c + 0] = fmaf(p, v.x, acc[4 * c + 0]);
                acc[4 * c + 1] = fmaf(p, v.y, acc[4 * c + 1]);
                acc[4 * c + 2] = fmaf(p, v.z, acc[4 * c + 2]);
                acc[4 * c + 3] = fmaf(p, v.w, acc[4 * c + 3]);
            }
        }
    }

    float linv = 1.f / sl[qi];
    float* orow = g_ol + ((long)(b * S_ + qs + qi)) * OLROW + h * RK;
#pragma unroll
    for (int c = 0; c < 16; c++) {
        float4 o;
        o.x = acc[4 * c + 0] * linv;
        o.y = acc[4 * c + 1] * linv;
        o.z = acc[4 * c + 2] * linv;
        o.w = acc[4 * c + 3] * linv;
        *(float4*)&orow[(g + 8 * c) * 4] = o;
    }
}

// ---------------- launch ----------------
extern "C" void kernel_launch(void* const* d_in, const int* in_sizes, int n_in,
                              void* d_out, int out_size)
{
    const float* x      = (const float*)d_in[0];
    const float* freqs  = (const float*)d_in[1];
    // d_in[2] = mask (unused; causal handled analytically)
    const float* wq_w   = (const float*)d_in[3];
    const float* wq_b   = (const float*)d_in[4];
    const float* wkva_w = (const float*)d_in[5];
    const float* wkva_b = (const float*)d_in[6];
    const float* knw    = (const float*)d_in[7];
    const float* wkvb   = (const float*)d_in[8];
    const float* wo_w   = (const float*)d_in[9];
    const float* wo_b   = (const float*)d_in[10];
    float* out = (float*)d_out;

    float *pq, *pqf, *pkv, *pol, *pov;
    cudaGetSymbolAddress((void**)&pq,  g_q);
    cudaGetSymbolAddress((void**)&pqf, g_qf);
    cudaGetSymbolAddress((void**)&pkv, g_kvt);
    cudaGetSymbolAddress((void**)&pol, g_ol);
    cudaGetSymbolAddress((void**)&pov, g_ov);

    const int FLASH_SMEM = (TQ * CDP + TK * CDP + TQ * TK + 3 * TQ) * (int)sizeof(float); // 113600
    cudaFuncSetAttribute(flash_attn, cudaFuncAttributeMaxDynamicSharedMemorySize, FLASH_SMEM);

    // 1) kv = x @ wkv_a_w^T + b  : (4096, 576)
    gemm_k<true, true><<<dim3(CD / 64, BS / 128, 1), 256>>>(
        D_, x, D_, 0, wkva_w, D_, 0, pkv, CD, 0, wkva_b, 1.f);

    // 2) rmsnorm latent + rope k_pe -> g_kf
    kv_post<<<BS, 128>>>(freqs, knw);

    // 3) q = x @ wq_w^T + b : (4096, 3072)
    gemm_k<true, true><<<dim3(QBROW / 64, BS / 128, 1), 256>>>(
        D_, x, D_, 0, wq_w, D_, 0, pq, QBROW, 0, wq_b, 1.f);

    // 4) rope q_pe (scaled) -> g_qf[..., 512:576]
    q_rope<<<BS, 512>>>(freqs);

    // 5) q_absorbed (per head): q_nope @ wkv_b_nope, scaled -> g_qf[..., :512]
    gemm_k<false, false><<<dim3(RK / 64, BS / 128, H_), 256>>>(
        NOPE_, pq, QBROW, QK_HD,
        wkvb, RK, (long)(NOPE_ + V_HD) * RK,
        pqf, QROW, CD, nullptr, SCALE_);

    // 6) causal flash MQA -> g_ol
    flash_attn<<<dim3(S_ / TQ, H_, B_), 128, FLASH_SMEM>>>();

    // 7) per-head V up-projection: o_lat @ wkv_b_v^T -> g_ov
    gemm_k<true, false><<<dim3(V_HD / 64, BS / 128, H_), 256>>>(
        RK, pol, OLROW, RK,
        wkvb + (long)NOPE_ * RK, RK, (long)(NOPE_ + V_HD) * RK,
        pov, OVROW, V_HD, nullptr, 1.f);

    // 8) final: g_ov @ wo_w^T + wo_b -> out
    gemm_k<true, true><<<dim3(D_ / 64, BS / 128, 1), 256>>>(
        OVROW, pov, OVROW, 0, wo_w, D_, 0, out, D_, 0, wo_b, 1.f);
}

// round 3
// speedup vs baseline: 2.5424x; 2.5424x over previous
#include <cuda_runtime.h>
#include <cuda_bf16.h>
#include <math.h>
#include <stdint.h>

// ---------------- problem constants ----------------
#define B_ 2
#define S_ 2048
#define D_ 2048
#define H_ 16
#define RK 512            // KV_RANK
#define ROPE_ 64
#define NOPE_ 128
#define QK_HD 192
#define V_HD 128
#define CD 576            // RK + ROPE (key dim)
#define BS (B_ * S_)      // 4096
#define QROW (H_ * CD)    // 9216
#define QBROW (H_ * QK_HD)// 3072
#define OLROW (H_ * RK)   // 8192
#define OVROW (H_ * V_HD) // 2048
#define EPS_ 1.1920929e-07f
#define SCALE_ 0.0721687836487032f   // 192^-0.5

// ---------------- scratch ----------------
__device__ float g_q   [(size_t)BS * QBROW];
__device__ float g_qf  [(size_t)BS * QROW];
__device__ float g_kvt [(size_t)BS * CD];
__device__ float g_kf  [(size_t)BS * CD];
__device__ float g_ol  [(size_t)BS * OLROW];
__device__ float g_ov  [(size_t)BS * OVROW];

// ---------------- helpers ----------------
__device__ __forceinline__ float tf32r(float x) {
    uint32_t u = __float_as_uint(x), o;
    asm("cvt.rna.tf32.f32 %0, %1;" : "=r"(o) : "r"(u));
    return __uint_as_float(o);
}

__device__ __forceinline__ void mma_tf32(float c[4],
    uint32_t a0, uint32_t a1, uint32_t a2, uint32_t a3,
    uint32_t b0, uint32_t b1)
{
    asm volatile("mma.sync.aligned.m16n8k8.row.col.f32.tf32.tf32.f32 "
        "{%0,%1,%2,%3}, {%4,%5,%6,%7}, {%8,%9}, {%0,%1,%2,%3};\n"
        : "+f"(c[0]), "+f"(c[1]), "+f"(c[2]), "+f"(c[3])
        : "r"(a0), "r"(a1), "r"(a2), "r"(a3), "r"(b0), "r"(b1));
}

// ---------------- tf32 tensor-core GEMM ----------------
// C = alpha * A * op(B) (+bias).  A:(M,K) row-major.
// TB ? B:(N,K) row-major : B:(K,N) row-major.
// Block tile 128(M) x 64(N) x 16(K). 256 threads = 8 warps (4m x 2n),
// warp tile 32x32 (2 m16 x 4 n8). All dims divide evenly for this problem.
template<bool TB, bool HASB>
__global__ __launch_bounds__(256)
void gemm_tc(int K,
             const float* __restrict__ A, int lda, long aB,
             const float* __restrict__ Bm, int ldb, long bB,
             float* __restrict__ C, int ldc, long cB,
             const float* __restrict__ bias, float alpha)
{
    __shared__ float sA[128 * 20];
    __shared__ float sB[64 * 20];

    int z = blockIdx.z;
    A  += (long)z * aB;
    Bm += (long)z * bB;
    C  += (long)z * cB;

    long m0 = (long)blockIdx.y * 128;
    long n0 = (long)blockIdx.x * 64;
    int tid = threadIdx.x;
    int w = tid >> 5, lane = tid & 31, gid = lane >> 2, tig = lane & 3;
    int wm = w & 3, wn = w >> 2;

    float acc[2][4][4];
#pragma unroll
    for (int mi = 0; mi < 2; mi++)
#pragma unroll
        for (int j = 0; j < 4; j++)
#pragma unroll
            for (int e = 0; e < 4; e++) acc[mi][j][e] = 0.f;

    for (int k0 = 0; k0 < K; k0 += 16) {
        // A tile: 128x16 -> sA[row*20 + k]
#pragma unroll
        for (int i = 0; i < 2; i++) {
            int f = tid + i * 256;
            int r = f >> 2, kq = (f & 3) * 4;
            float4 v = *(const float4*)&A[(m0 + r) * (long)lda + k0 + kq];
            float4 t;
            t.x = tf32r(v.x); t.y = tf32r(v.y); t.z = tf32r(v.z); t.w = tf32r(v.w);
            *(float4*)&sA[r * 20 + kq] = t;
        }
        // B tile: 64x16 -> sB[n*20 + k]
        if (TB) {
            int r = tid >> 2, kq = (tid & 3) * 4;
            float4 v = *(const float4*)&Bm[(n0 + r) * (long)ldb + k0 + kq];
            float4 t;
            t.x = tf32r(v.x); t.y = tf32r(v.y); t.z = tf32r(v.z); t.w = tf32r(v.w);
            *(float4*)&sB[r * 20 + kq] = t;
        } else {
#pragma unroll
            for (int i = 0; i < 4; i++) {
                int kk = (tid >> 6) + i * 4, n = tid & 63;
                sB[n * 20 + kk] = tf32r(Bm[(long)(k0 + kk) * ldb + n0 + n]);
            }
        }
        __syncthreads();

#pragma unroll
        for (int kk = 0; kk < 2; kk++) {
            uint32_t a[2][4], b[4][2];
#pragma unroll
            for (int mi = 0; mi < 2; mi++) {
                int rb = wm * 32 + mi * 16 + gid;
                a[mi][0] = __float_as_uint(sA[rb * 20 + kk * 8 + tig]);
                a[mi][1] = __float_as_uint(sA[(rb + 8) * 20 + kk * 8 + tig]);
                a[mi][2] = __float_as_uint(sA[rb * 20 + kk * 8 + tig + 4]);
                a[mi][3] = __float_as_uint(sA[(rb + 8) * 20 + kk * 8 + tig + 4]);
            }
#pragma unroll
            for (int j = 0; j < 4; j++) {
                int nb = wn * 32 + j * 8 + gid;
                b[j][0] = __float_as_uint(sB[nb * 20 + kk * 8 + tig]);
                b[j][1] = __float_as_uint(sB[nb * 20 + kk * 8 + tig + 4]);
            }
#pragma unroll
            for (int mi = 0; mi < 2; mi++)
#pragma unroll
                for (int j = 0; j < 4; j++)
                    mma_tf32(acc[mi][j], a[mi][0], a[mi][1], a[mi][2], a[mi][3],
                             b[j][0], b[j][1]);
        }
        __syncthreads();
    }

    // epilogue
#pragma unroll
    for (int mi = 0; mi < 2; mi++) {
#pragma unroll
        for (int j = 0; j < 4; j++) {
            long col = n0 + wn * 32 + j * 8 + 2 * tig;
            float bx = 0.f, by = 0.f;
            if (HASB) { bx = bias[col]; by = bias[col + 1]; }
            long r0 = m0 + wm * 32 + mi * 16 + gid;
            float2 v0 = { acc[mi][j][0] * alpha + bx, acc[mi][j][1] * alpha + by };
            float2 v1 = { acc[mi][j][2] * alpha + bx, acc[mi][j][3] * alpha + by };
            *(float2*)&C[r0 * (long)ldc + col] = v0;
            *(float2*)&C[(r0 + 8) * (long)ldc + col] = v1;
        }
    }
}

// ---------------- kv post: rmsnorm latent + rope k_pe -> g_kf ----------------
__global__ __launch_bounds__(128)
void kv_post(const float* __restrict__ freqs, const float* __restrict__ knw)
{
    int bs = blockIdx.x;
    int s = bs & (S_ - 1);
    int tid = threadIdx.x;
    const float* row = g_kvt + (long)bs * CD;
    float*       out = g_kf  + (long)bs * CD;

    float ss = 0.f;
    for (int i = tid; i < RK; i += 128) { float v = row[i]; ss += v * v; }
    __shared__ float red[128];
    red[tid] = ss;
    __syncthreads();
    for (int o = 64; o > 0; o >>= 1) {
        if (tid < o) red[tid] += red[tid + o];
        __syncthreads();
    }
    __shared__ float rinv;
    if (tid == 0) rinv = rsqrtf(red[0] * (1.0f / RK) + EPS_);
    __syncthreads();
    float rv = rinv;
    for (int i = tid; i < RK; i += 128) out[i] = row[i] * rv * knw[i];

    if (tid < ROPE_ / 2) {
        float a = row[RK + 2 * tid];
        float b = row[RK + 2 * tid + 1];
        float f = freqs[(long)s * (ROPE_ / 2) + tid];
        float sn, cs;
        sincosf(f, &sn, &cs);
        out[RK + 2 * tid]     = a * cs - b * sn;
        out[RK + 2 * tid + 1] = a * sn + b * cs;
    }
}

// ---------------- q rope ----------------
__global__ __launch_bounds__(512)
void q_rope(const float* __restrict__ freqs)
{
    int bs = blockIdx.x;
    int s = bs & (S_ - 1);
    int tid = threadIdx.x;
    int h = tid >> 5, i = tid & 31;
    const float* qr = g_q + (long)bs * QBROW + h * QK_HD + NOPE_;
    float a = qr[2 * i], b = qr[2 * i + 1];
    float f = freqs[(long)s * (ROPE_ / 2) + i];
    float sn, cs;
    sincosf(f, &sn, &cs);
    float* o = g_qf + (long)bs * QROW + h * CD + RK;
    o[2 * i]     = (a * cs - b * sn) * SCALE_;
    o[2 * i + 1] = (a * sn + b * cs) * SCALE_;
}

// ---------------- tensor-core causal flash MQA ----------------
// Block: 4 tokens x ALL 16 heads = 64 query rows sharing one K/V tile.
// row = tok*16 + h, so warp m-group (16 rows) == one token -> uniform causal
// mask per warp. 256 threads = 8 warps (4m x 2n).
// Scores: S(64x16) per iter; warp computes 16x8 (wn half).
// PV: O(64x512); warp computes 16x256 -> 128 acc regs/thread.
// sq dim-major pitch 72, sk keys-major pitch 584, sP pitch 20:
// all fragment LDS patterns conflict-free.
#define SQN (576 * 72)
#define SKN (16 * 584)
#define SPN (64 * 20)
#define FLASH_SMEM_FL (SQN + SKN + SPN + 3 * 64)

__global__ __launch_bounds__(256)
void flash_tc()
{
    extern __shared__ float fs[];
    float* sq  = fs;
    float* sk  = sq + SQN;
    float* sP  = sk + SKN;
    float* smx = sP + SPN;
    float* sl  = smx + 64;
    float* sal = sl + 64;

    int qs = blockIdx.x * 4;       // token base
    int b  = blockIdx.y;
    int tid = threadIdx.x;
    int w = tid >> 5, lane = tid & 31, gid = lane >> 2, tig = lane & 3;
    int wm = w & 3, wn = w >> 2;

    // load q: 64 rows x 576 dims -> sq[d*72 + row] (tf32)
    {
        const float* qb = g_qf + ((long)(b * S_ + qs)) * QROW;
        for (int f = tid; f < 64 * 144; f += 256) {
            int row = f / 144, d4 = (f % 144) * 4;
            int tok = row >> 4, h = row & 15;
            float4 v = *(const float4*)&qb[(long)tok * QROW + h * CD + d4];
            sq[(d4 + 0) * 72 + row] = tf32r(v.x);
            sq[(d4 + 1) * 72 + row] = tf32r(v.y);
            sq[(d4 + 2) * 72 + row] = tf32r(v.z);
            sq[(d4 + 3) * 72 + row] = tf32r(v.w);
        }
        if (tid < 64) { smx[tid] = -3.0e38f; sl[tid] = 0.f; }
    }

    float oacc[32][4];
#pragma unroll
    for (int j = 0; j < 32; j++) {
        oacc[j][0] = 0.f; oacc[j][1] = 0.f; oacc[j][2] = 0.f; oacc[j][3] = 0.f;
    }

    const float* kb = g_kf + (long)b * S_ * CD;
    int ntk = (qs + 3) / 16 + 1;
    int qtok = qs + wm;            // this warp's query token

    for (int kt = 0; kt < ntk; kt++) {
        int t0 = kt * 16;
        __syncthreads();   // prev PV done -> safe to overwrite sk/sP
        for (int f = tid; f < 16 * 144; f += 256) {
            int r = f / 144, c4 = (f % 144) * 4;
            float4 v = *(const float4*)&kb[(long)(t0 + r) * CD + c4];
            float4 t;
            t.x = tf32r(v.x); t.y = tf32r(v.y); t.z = tf32r(v.z); t.w = tf32r(v.w);
            *(float4*)&sk[r * 584 + c4] = t;
        }
        __syncthreads();

        // ---- scores: warp tile 16x8, K-dim 576 (72 k8 steps, 4 accum splits) ----
        float sc[4][4];
#pragma unroll
        for (int p = 0; p < 4; p++)
#pragma unroll
            for (int e = 0; e < 4; e++) sc[p][e] = 0.f;
        {
            int rb = wm * 16 + gid;
            int nb = wn * 8 + gid;
#pragma unroll 8
            for (int kk = 0; kk < 72; kk++) {
                uint32_t a0 = __float_as_uint(sq[(kk * 8 + tig) * 72 + rb]);
                uint32_t a1 = __float_as_uint(sq[(kk * 8 + tig) * 72 + rb + 8]);
                uint32_t a2 = __float_as_uint(sq[(kk * 8 + tig + 4) * 72 + rb]);
                uint32_t a3 = __float_as_uint(sq[(kk * 8 + tig + 4) * 72 + rb + 8]);
                uint32_t b0 = __float_as_uint(sk[nb * 584 + kk * 8 + tig]);
                uint32_t b1 = __float_as_uint(sk[nb * 584 + kk * 8 + tig + 4]);
                mma_tf32(sc[kk & 3], a0, a1, a2, a3, b0, b1);
            }
        }
        {
            float s0 = sc[0][0] + sc[1][0] + sc[2][0] + sc[3][0];
            float s1 = sc[0][1] + sc[1][1] + sc[2][1] + sc[3][1];
            float s2 = sc[0][2] + sc[1][2] + sc[2][2] + sc[3][2];
            float s3 = sc[0][3] + sc[1][3] + sc[2][3] + sc[3][3];
            int c0 = wn * 8 + 2 * tig, c1 = c0 + 1;
            bool m0ok = (t0 + c0) <= qtok;
            bool m1ok = (t0 + c1) <= qtok;
            int r0 = wm * 16 + gid;
            sP[r0 * 20 + c0]       = m0ok ? s0 : -3.0e38f;
            sP[r0 * 20 + c1]       = m1ok ? s1 : -3.0e38f;
            sP[(r0 + 8) * 20 + c0] = m0ok ? s2 : -3.0e38f;
            sP[(r0 + 8) * 20 + c1] = m1ok ? s3 : -3.0e38f;
        }
        __syncthreads();

        // ---- online softmax, one thread per row ----
        if (tid < 64) {
            float mo = smx[tid], mx = mo;
#pragma unroll
            for (int j = 0; j < 16; j++) mx = fmaxf(mx, sP[tid * 20 + j]);
            float al = __expf(mo - mx);
            float sum = 0.f;
#pragma unroll
            for (int j = 0; j < 16; j++) {
                float p = __expf(sP[tid * 20 + j] - mx);
                sP[tid * 20 + j] = tf32r(p);
                sum += p;
            }
            smx[tid] = mx;
            sl[tid]  = sl[tid] * al + sum;
            sal[tid] = al;
        }
        __syncthreads();

        // ---- rescale + PV: O(16x256 per warp) += P(16x16) @ V(16x512) ----
        {
            float al0 = sal[wm * 16 + gid];
            float al1 = sal[wm * 16 + gid + 8];
#pragma unroll
            for (int j = 0; j < 32; j++) {
                oacc[j][0] *= al0; oacc[j][1] *= al0;
                oacc[j][2] *= al1; oacc[j][3] *= al1;
            }
            int rb = wm * 16 + gid;
#pragma unroll
            for (int kk = 0; kk < 2; kk++) {
                uint32_t a0 = __float_as_uint(sP[rb * 20 + kk * 8 + tig]);
                uint32_t a1 = __float_as_uint(sP[(rb + 8) * 20 + kk * 8 + tig]);
                uint32_t a2 = __float_as_uint(sP[rb * 20 + kk * 8 + tig + 4]);
                uint32_t a3 = __float_as_uint(sP[(rb + 8) * 20 + kk * 8 + tig + 4]);
#pragma unroll
                for (int j = 0; j < 32; j++) {
                    int nb2 = wn * 256 + j * 8 + gid;
                    uint32_t b0 = __float_as_uint(sk[(kk * 8 + tig) * 584 + nb2]);
                    uint32_t b1 = __float_as_uint(sk[(kk * 8 + tig + 4) * 584 + nb2]);
                    mma_tf32(oacc[j], a0, a1, a2, a3, b0, b1);
                }
            }
        }
    }

    // ---- write out: row (tok=wm, h=gid / gid+8) ----
    {
        float l0 = 1.f / sl[wm * 16 + gid];
        float l1 = 1.f / sl[wm * 16 + gid + 8];
        long base = ((long)(b * S_ + qs + wm)) * OLROW;
        long b0a = base + (long)gid * RK;
        long b1a = base + (long)(gid + 8) * RK;
#pragma unroll
        for (int j = 0; j < 32; j++) {
            int col = wn * 256 + j * 8 + 2 * tig;
            float2 v0 = { oacc[j][0] * l0, oacc[j][1] * l0 };
            float2 v1 = { oacc[j][2] * l1, oacc[j][3] * l1 };
            *(float2*)&g_ol[b0a + col] = v0;
            *(float2*)&g_ol[b1a + col] = v1;
        }
    }
}

// ---------------- launch ----------------
extern "C" void kernel_launch(void* const* d_in, const int* in_sizes, int n_in,
                              void* d_out, int out_size)
{
    const float* x      = (const float*)d_in[0];
    const float* freqs  = (const float*)d_in[1];
    // d_in[2] = mask (unused; causal handled analytically)
    const float* wq_w   = (const float*)d_in[3];
    const float* wq_b   = (const float*)d_in[4];
    const float* wkva_w = (const float*)d_in[5];
    const float* wkva_b = (const float*)d_in[6];
    const float* knw    = (const float*)d_in[7];
    const float* wkvb   = (const float*)d_in[8];
    const float* wo_w   = (const float*)d_in[9];
    const float* wo_b   = (const float*)d_in[10];
    float* out = (float*)d_out;

    float *pq, *pqf, *pkv, *pol, *pov;
    cudaGetSymbolAddress((void**)&pq,  g_q);
    cudaGetSymbolAddress((void**)&pqf, g_qf);
    cudaGetSymbolAddress((void**)&pkv, g_kvt);
    cudaGetSymbolAddress((void**)&pol, g_ol);
    cudaGetSymbolAddress((void**)&pov, g_ov);

    const int FLASH_SMEM = FLASH_SMEM_FL * (int)sizeof(float); // 209,920-ish
    cudaFuncSetAttribute(flash_tc, cudaFuncAttributeMaxDynamicSharedMemorySize, FLASH_SMEM);

    // 1) kv = x @ wkv_a_w^T + b : (4096, 576)
    gemm_tc<true, true><<<dim3(CD / 64, BS / 128, 1), 256>>>(
        D_, x, D_, 0, wkva_w, D_, 0, pkv, CD, 0, wkva_b, 1.f);

    // 2) rmsnorm latent + rope k_pe -> g_kf
    kv_post<<<BS, 128>>>(freqs, knw);

    // 3) q = x @ wq_w^T + b : (4096, 3072)
    gemm_tc<true, true><<<dim3(QBROW / 64, BS / 128, 1), 256>>>(
        D_, x, D_, 0, wq_w, D_, 0, pq, QBROW, 0, wq_b, 1.f);

    // 4) rope q_pe (scaled) -> g_qf[..., 512:576]
    q_rope<<<BS, 512>>>(freqs);

    // 5) q_absorbed per head: q_nope @ wkv_b_nope, scaled -> g_qf[..., :512]
    gemm_tc<false, false><<<dim3(RK / 64, BS / 128, H_), 256>>>(
        NOPE_, pq, QBROW, QK_HD,
        wkvb, RK, (long)(NOPE_ + V_HD) * RK,
        pqf, QROW, CD, nullptr, SCALE_);

    // 6) causal flash MQA (tensor cores) -> g_ol
    flash_tc<<<dim3(S_ / 4, B_), 256, FLASH_SMEM>>>();

    // 7) per-head V up-projection: o_lat @ wkv_b_v^T -> g_ov
    gemm_tc<true, false><<<dim3(V_HD / 64, BS / 128, H_), 256>>>(
        RK, pol, OLROW, RK,
        wkvb + (long)NOPE_ * RK, RK, (long)(NOPE_ + V_HD) * RK,
        pov, OVROW, V_HD, nullptr, 1.f);

    // 8) final: g_ov @ wo_w^T + wo_b -> out
    gemm_tc<true, true><<<dim3(D_ / 64, BS / 128, 1), 256>>>(
        OVROW, pov, OVROW, 0, wo_w, D_, 0, out, D_, 0, wo_b, 1.f);
}

// round 5
// speedup vs baseline: 4.3980x; 1.7298x over previous
#include <cuda_runtime.h>
#include <cuda_bf16.h>
#include <math.h>
#include <stdint.h>

// ---------------- problem constants ----------------
#define B_ 2
#define S_ 2048
#define D_ 2048
#define H_ 16
#define RK 512
#define ROPE_ 64
#define NOPE_ 128
#define QK_HD 192
#define V_HD 128
#define CD 576            // RK + ROPE
#define BS (B_ * S_)      // 4096
#define QROW (H_ * CD)    // 9216
#define QBROW (H_ * QK_HD)// 3072
#define OLROW (H_ * RK)   // 8192
#define OVROW (H_ * V_HD) // 2048
#define EPS_ 1.1920929e-07f
#define SCALE_ 0.0721687836487032f

// ---------------- scratch ----------------
__device__ float g_q   [(size_t)BS * QBROW];   // raw fp32
__device__ float g_qf  [(size_t)BS * QROW];    // tf32-rounded (flash input)
__device__ float g_kvt [(size_t)BS * CD];      // raw fp32
__device__ float g_kf  [(size_t)BS * CD];      // tf32-rounded (flash input)
__device__ float g_ol  [(size_t)BS * OLROW];   // raw fp32
__device__ float g_ov  [(size_t)BS * OVROW];   // raw fp32

// ---------------- helpers ----------------
__device__ __forceinline__ float tf32r(float x) {
    uint32_t u = __float_as_uint(x), o;
    asm("cvt.rna.tf32.f32 %0, %1;" : "=r"(o) : "r"(u));
    return __uint_as_float(o);
}
__device__ __forceinline__ void split2(float v, uint32_t& hi, uint32_t& lo) {
    float h = tf32r(v);
    hi = __float_as_uint(h);
    lo = __float_as_uint(tf32r(v - h));
}
__device__ __forceinline__ void mma_tf32(float c[4],
    uint32_t a0, uint32_t a1, uint32_t a2, uint32_t a3,
    uint32_t b0, uint32_t b1)
{
    asm volatile("mma.sync.aligned.m16n8k8.row.col.f32.tf32.tf32.f32 "
        "{%0,%1,%2,%3}, {%4,%5,%6,%7}, {%8,%9}, {%0,%1,%2,%3};\n"
        : "+f"(c[0]), "+f"(c[1]), "+f"(c[2]), "+f"(c[3])
        : "r"(a0), "r"(a1), "r"(a2), "r"(a3), "r"(b0), "r"(b1));
}
__device__ __forceinline__ uint32_t sm_u32(const void* p) {
    return (uint32_t)__cvta_generic_to_shared(p);
}
#define CPA16(d, s) asm volatile("cp.async.ca.shared.global [%0], [%1], 16;\n" :: "r"(d), "l"(s))
#define CPCOMMIT()  asm volatile("cp.async.commit_group;\n")
#define CPWAIT(n)   asm volatile("cp.async.wait_group %0;\n" :: "n"(n))

// ---------------- split-precision pipelined GEMM (fp32-accurate) ----------------
// C = alpha * A*op(B) (+bias). A:(M,K) rm raw fp32. TB ? B:(N,K) rm : B:(K,N) rm.
// 128x64x16 tile, 3-stage cp.async. Fragments split hi/lo -> 3 mma (hh+hl+lh).
#define GA_ST 2560            // 128*20 floats per A stage
#define GB_ST 1280            // >= max(64*20, 16*72)
template<bool TB, bool HASB, bool RND>
__global__ __launch_bounds__(256)
void gemm_sp(int K,
             const float* __restrict__ A, int lda, long aB,
             const float* __restrict__ Bm, int ldb, long bB,
             float* __restrict__ C, int ldc, long cB,
             const float* __restrict__ bias, float alpha)
{
    __shared__ float sA[3 * GA_ST];
    __shared__ float sB[3 * GB_ST];

    int z = blockIdx.z;
    A  += (long)z * aB;
    Bm += (long)z * bB;
    C  += (long)z * cB;

    long m0 = (long)blockIdx.y * 128;
    long n0 = (long)blockIdx.x * 64;
    int tid = threadIdx.x;
    int w = tid >> 5, lane = tid & 31, gid = lane >> 2, tig = lane & 3;
    int wm = w & 3, wn = w >> 2;

    uint32_t sAu = sm_u32(sA), sBu = sm_u32(sB);
    int nk = K / 16;

    auto issue = [&](int s, int kt) {
        int k0 = kt * 16;
#pragma unroll
        for (int i = 0; i < 2; i++) {
            int c = tid + i * 256;
            int r = c >> 2, kq = (c & 3) * 4;
            CPA16(sAu + (s * GA_ST + r * 20 + kq) * 4,
                  &A[(m0 + r) * (long)lda + k0 + kq]);
        }
        if (TB) {
            int r = tid >> 2, kq = (tid & 3) * 4;
            CPA16(sBu + (s * GB_ST + r * 20 + kq) * 4,
                  &Bm[(n0 + r) * (long)ldb + k0 + kq]);
        } else {
            int kk = tid >> 4, nq = (tid & 15) * 4;
            CPA16(sBu + (s * GB_ST + kk * 72 + nq) * 4,
                  &Bm[(long)(k0 + kk) * (long)ldb + n0 + nq]);
        }
    };

    float acc[2][4][4];
#pragma unroll
    for (int mi = 0; mi < 2; mi++)
#pragma unroll
        for (int j = 0; j < 4; j++)
#pragma unroll
            for (int e = 0; e < 4; e++) acc[mi][j][e] = 0.f;

    issue(0, 0); CPCOMMIT();
    if (nk > 1) { issue(1, 1); CPCOMMIT(); }

    for (int kt = 0; kt < nk; kt++) {
        CPWAIT(1);
        __syncthreads();
        if (kt + 2 < nk) { issue((kt + 2) % 3, kt + 2); CPCOMMIT(); }

        const float* cA = sA + (kt % 3) * GA_ST;
        const float* cB = sB + (kt % 3) * GB_ST;
#pragma unroll
        for (int kk = 0; kk < 2; kk++) {
            uint32_t ahi[2][4], alo[2][4], bhi[4][2], blo[4][2];
#pragma unroll
            for (int mi = 0; mi < 2; mi++) {
                int rb = wm * 32 + mi * 16 + gid;
                split2(cA[rb * 20 + kk * 8 + tig],           ahi[mi][0], alo[mi][0]);
                split2(cA[(rb + 8) * 20 + kk * 8 + tig],     ahi[mi][1], alo[mi][1]);
                split2(cA[rb * 20 + kk * 8 + tig + 4],       ahi[mi][2], alo[mi][2]);
                split2(cA[(rb + 8) * 20 + kk * 8 + tig + 4], ahi[mi][3], alo[mi][3]);
            }
#pragma unroll
            for (int j = 0; j < 4; j++) {
                int nb = wn * 32 + j * 8 + gid;
                if (TB) {
                    split2(cB[nb * 20 + kk * 8 + tig],     bhi[j][0], blo[j][0]);
                    split2(cB[nb * 20 + kk * 8 + tig + 4], bhi[j][1], blo[j][1]);
                } else {
                    split2(cB[(kk * 8 + tig) * 72 + nb],     bhi[j][0], blo[j][0]);
                    split2(cB[(kk * 8 + tig + 4) * 72 + nb], bhi[j][1], blo[j][1]);
                }
            }
#pragma unroll
            for (int mi = 0; mi < 2; mi++)
#pragma unroll
                for (int j = 0; j < 4; j++) {
                    // correction terms first, then main (order irrelevant for fp32 acc)
                    mma_tf32(acc[mi][j], ahi[mi][0], ahi[mi][1], ahi[mi][2], ahi[mi][3],
                             blo[j][0], blo[j][1]);
                    mma_tf32(acc[mi][j], alo[mi][0], alo[mi][1], alo[mi][2], alo[mi][3],
                             bhi[j][0], bhi[j][1]);
                    mma_tf32(acc[mi][j], ahi[mi][0], ahi[mi][1], ahi[mi][2], ahi[mi][3],
                             bhi[j][0], bhi[j][1]);
                }
        }
        __syncthreads();
    }

#pragma unroll
    for (int mi = 0; mi < 2; mi++) {
#pragma unroll
        for (int j = 0; j < 4; j++) {
            long col = n0 + wn * 32 + j * 8 + 2 * tig;
            float bx = 0.f, by = 0.f;
            if (HASB) { bx = bias[col]; by = bias[col + 1]; }
            long r0 = m0 + wm * 32 + mi * 16 + gid;
            float v0x = acc[mi][j][0] * alpha + bx, v0y = acc[mi][j][1] * alpha + by;
            float v1x = acc[mi][j][2] * alpha + bx, v1y = acc[mi][j][3] * alpha + by;
            if (RND) { v0x = tf32r(v0x); v0y = tf32r(v0y); v1x = tf32r(v1x); v1y = tf32r(v1y); }
            float2 v0 = { v0x, v0y }, v1 = { v1x, v1y };
            *(float2*)&C[r0 * (long)ldc + col] = v0;
            *(float2*)&C[(r0 + 8) * (long)ldc + col] = v1;
        }
    }
}

// ---------------- kv post: rmsnorm latent + rope k_pe -> g_kf (tf32) ----------------
// input g_kvt is RAW fp32; outputs rounded once for flash.
__global__ __launch_bounds__(128)
void kv_post(const float* __restrict__ freqs, const float* __restrict__ knw)
{
    int bs = blockIdx.x;
    int s = bs & (S_ - 1);
    int tid = threadIdx.x;
    const float* row = g_kvt + (long)bs * CD;
    float*       out = g_kf  + (long)bs * CD;

    float ss = 0.f;
    for (int i = tid; i < RK; i += 128) { float v = row[i]; ss += v * v; }
    __shared__ float red[128];
    red[tid] = ss;
    __syncthreads();
    for (int o = 64; o > 0; o >>= 1) {
        if (tid < o) red[tid] += red[tid + o];
        __syncthreads();
    }
    __shared__ float rinv;
    if (tid == 0) rinv = rsqrtf(red[0] * (1.0f / RK) + EPS_);
    __syncthreads();
    float rv = rinv;
    for (int i = tid; i < RK; i += 128) out[i] = tf32r(row[i] * rv * knw[i]);

    if (tid < ROPE_ / 2) {
        float a = row[RK + 2 * tid];
        float b = row[RK + 2 * tid + 1];
        float f = freqs[(long)s * (ROPE_ / 2) + tid];
        float sn, cs;
        sincosf(f, &sn, &cs);
        out[RK + 2 * tid]     = tf32r(a * cs - b * sn);
        out[RK + 2 * tid + 1] = tf32r(a * sn + b * cs);
    }
}

// ---------------- q rope (raw in, scaled, tf32 out) ----------------
__global__ __launch_bounds__(512)
void q_rope(const float* __restrict__ freqs)
{
    int bs = blockIdx.x;
    int s = bs & (S_ - 1);
    int tid = threadIdx.x;
    int h = tid >> 5, i = tid & 31;
    const float* qr = g_q + (long)bs * QBROW + h * QK_HD + NOPE_;
    float a = qr[2 * i], b = qr[2 * i + 1];
    float f = freqs[(long)s * (ROPE_ / 2) + i];
    float sn, cs;
    sincosf(f, &sn, &cs);
    float* o = g_qf + (long)bs * QROW + h * CD + RK;
    o[2 * i]     = tf32r((a * cs - b * sn) * SCALE_);
    o[2 * i + 1] = tf32r((a * sn + b * cs) * SCALE_);
}

// ---------------- flash MQA (single-tf32, inputs pre-rounded) ----------------
// Block: 4 tokens x 16 heads = 64 q-rows. TK=32 keys per tile, cp.async.
// smem: sq 64x580 rm, sk 32x580 rm (V = cols 0..511), sP 64x36 (stats cols 32..34).
// Scores: warps 0..3, 16 rows x 32 keys each, 72 k8 steps.
// PV: all 8 warps, each 64 rows x 64 V-cols (B-frags shared across 4 row-groups).
#define FP 580
#define SQF (64 * FP)
#define SKF (32 * FP)
#define SPF (64 * 36)
#define FLASH_FLOATS (SQF + SKF + SPF)   // 57984 floats = 231936 B

__global__ __launch_bounds__(256, 1)
void flash_tc()
{
    extern __shared__ float fs[];
    float* sq = fs;
    float* sk = sq + SQF;
    float* sP = sk + SKF;

    int qs = blockIdx.x * 4;
    int b  = blockIdx.y;
    int tid = threadIdx.x;
    int w = tid >> 5, lane = tid & 31, gid = lane >> 2, tig = lane & 3;

    uint32_t squ = sm_u32(sq), sku = sm_u32(sk);
    const float* qb = g_qf + ((long)(b * S_ + qs)) * QROW;
    const float* kb = g_kf + (long)b * S_ * CD;

    for (int c = tid; c < 64 * 144; c += 256) {
        int row = c / 144, cq = (c % 144) * 4;
        int tok = row >> 4, h = row & 15;
        CPA16(squ + (row * FP + cq) * 4, &qb[(long)tok * QROW + h * CD + cq]);
    }
    for (int c = tid; c < 32 * 144; c += 256) {
        int r = c / 144, cq = (c % 144) * 4;
        CPA16(sku + (r * FP + cq) * 4, &kb[(long)r * CD + cq]);
    }
    CPCOMMIT();
    if (tid < 64) { sP[tid * 36 + 32] = -3.0e38f; sP[tid * 36 + 33] = 0.f; }

    float oacc[4][8][4];
#pragma unroll
    for (int rg = 0; rg < 4; rg++)
#pragma unroll
        for (int j = 0; j < 8; j++)
#pragma unroll
            for (int e = 0; e < 4; e++) oacc[rg][j][e] = 0.f;

    int ntk = qs / 32 + 1;

    for (int kt = 0; kt < ntk; kt++) {
        int t0 = kt * 32;
        CPWAIT(0);
        __syncthreads();

        if (w < 4) {
            int rb = w * 16;
            const float* r0p = sq + (rb + gid) * FP;
            const float* r1p = sq + (rb + gid + 8) * FP;
            float sc[4][4];
#pragma unroll
            for (int j = 0; j < 4; j++)
#pragma unroll
                for (int e = 0; e < 4; e++) sc[j][e] = 0.f;
#pragma unroll 8
            for (int kk = 0; kk < 72; kk++) {
                int kc = kk * 8;
                uint32_t a0 = __float_as_uint(r0p[kc + tig]);
                uint32_t a1 = __float_as_uint(r1p[kc + tig]);
                uint32_t a2 = __float_as_uint(r0p[kc + tig + 4]);
                uint32_t a3 = __float_as_uint(r1p[kc + tig + 4]);
#pragma unroll
                for (int j = 0; j < 4; j++) {
                    uint32_t b0 = __float_as_uint(sk[(j * 8 + gid) * FP + kc + tig]);
                    uint32_t b1 = __float_as_uint(sk[(j * 8 + gid) * FP + kc + tig + 4]);
                    mma_tf32(sc[j], a0, a1, a2, a3, b0, b1);
                }
            }
#pragma unroll
            for (int j = 0; j < 4; j++) {
                int c0 = j * 8 + 2 * tig;
                float2 v0 = { sc[j][0], sc[j][1] };
                float2 v1 = { sc[j][2], sc[j][3] };
                *(float2*)&sP[(rb + gid) * 36 + c0] = v0;
                *(float2*)&sP[(rb + gid + 8) * 36 + c0] = v1;
            }
        }
        __syncthreads();

        if (tid < 64) {
            int row = tid;
            int spos = qs + (row >> 4);
            float* pr = sP + row * 36;
            float v[32];
            float mo = pr[32], mx = mo;
#pragma unroll
            for (int j = 0; j < 32; j++) {
                float x = pr[j];
                if (t0 + j > spos) x = -1.0e30f;
                v[j] = x;
                mx = fmaxf(mx, x);
            }
            float al = __expf(mo - mx);
            float sum = 0.f;
#pragma unroll
            for (int j = 0; j < 32; j++) {
                float p = __expf(v[j] - mx);
                sum += p;
                pr[j] = tf32r(p);
            }
            pr[32] = mx;
            pr[33] = pr[33] * al + sum;
            pr[34] = al;
        }
        __syncthreads();

        {
            float al0[4], al1[4];
#pragma unroll
            for (int rg = 0; rg < 4; rg++) {
                al0[rg] = sP[(rg * 16 + gid) * 36 + 34];
                al1[rg] = sP[(rg * 16 + gid + 8) * 36 + 34];
            }
#pragma unroll
            for (int rg = 0; rg < 4; rg++)
#pragma unroll
                for (int j = 0; j < 8; j++) {
                    oacc[rg][j][0] *= al0[rg]; oacc[rg][j][1] *= al0[rg];
                    oacc[rg][j][2] *= al1[rg]; oacc[rg][j][3] *= al1[rg];
                }
#pragma unroll
            for (int kk = 0; kk < 4; kk++) {
                int kc = kk * 8;
                uint32_t A0[4], A1[4], A2[4], A3[4];
#pragma unroll
                for (int rg = 0; rg < 4; rg++) {
                    A0[rg] = __float_as_uint(sP[(rg * 16 + gid) * 36 + kc + tig]);
                    A1[rg] = __float_as_uint(sP[(rg * 16 + gid + 8) * 36 + kc + tig]);
                    A2[rg] = __float_as_uint(sP[(rg * 16 + gid) * 36 + kc + tig + 4]);
                    A3[rg] = __float_as_uint(sP[(rg * 16 + gid + 8) * 36 + kc + tig + 4]);
                }
#pragma unroll
                for (int j = 0; j < 8; j++) {
                    int col = w * 64 + j * 8 + gid;
                    uint32_t b0 = __float_as_uint(sk[(kc + tig) * FP + col]);
                    uint32_t b1 = __float_as_uint(sk[(kc + tig + 4) * FP + col]);
#pragma unroll
                    for (int rg = 0; rg < 4; rg++)
                        mma_tf32(oacc[rg][j], A0[rg], A1[rg], A2[rg], A3[rg], b0, b1);
                }
            }
        }
        __syncthreads();

        if (kt + 1 < ntk) {
            int tn = t0 + 32;
            for (int c = tid; c < 32 * 144; c += 256) {
                int r = c / 144, cq = (c % 144) * 4;
                CPA16(sku + (r * FP + cq) * 4, &kb[(long)(tn + r) * CD + cq]);
            }
        }
        CPCOMMIT();
    }

    // epilogue: normalize + write RAW fp32 (consumer GEMM splits at load)
#pragma unroll
    for (int rg = 0; rg < 4; rg++) {
        float l0 = 1.f / sP[(rg * 16 + gid) * 36 + 33];
        float l1 = 1.f / sP[(rg * 16 + gid + 8) * 36 + 33];
        long base = ((long)(b * S_ + qs + rg)) * OLROW;
        float* o0 = g_ol + base + (long)gid * RK + w * 64;
        float* o1 = g_ol + base + (long)(gid + 8) * RK + w * 64;
#pragma unroll
        for (int j = 0; j < 8; j++) {
            int col = j * 8 + 2 * tig;
            float2 v0 = { oacc[rg][j][0] * l0, oacc[rg][j][1] * l0 };
            float2 v1 = { oacc[rg][j][2] * l1, oacc[rg][j][3] * l1 };
            *(float2*)&o0[col] = v0;
            *(float2*)&o1[col] = v1;
        }
    }
}

// ---------------- launch ----------------
extern "C" void kernel_launch(void* const* d_in, const int* in_sizes, int n_in,
                              void* d_out, int out_size)
{
    const float* x      = (const float*)d_in[0];
    const float* freqs  = (const float*)d_in[1];
    // d_in[2] = mask (causal handled analytically)
    const float* wq_w   = (const float*)d_in[3];
    const float* wq_b   = (const float*)d_in[4];
    const float* wkva_w = (const float*)d_in[5];
    const float* wkva_b = (const float*)d_in[6];
    const float* knw    = (const float*)d_in[7];
    const float* wkvb   = (const float*)d_in[8];
    const float* wo_w   = (const float*)d_in[9];
    const float* wo_b   = (const float*)d_in[10];
    float* out = (float*)d_out;

    float *pq, *pqf, *pkv, *pol, *pov;
    cudaGetSymbolAddress((void**)&pq,  g_q);
    cudaGetSymbolAddress((void**)&pqf, g_qf);
    cudaGetSymbolAddress((void**)&pkv, g_kvt);
    cudaGetSymbolAddress((void**)&pol, g_ol);
    cudaGetSymbolAddress((void**)&pov, g_ov);

    const int FLASH_SMEM = FLASH_FLOATS * (int)sizeof(float); // 231936
    cudaFuncSetAttribute(flash_tc, cudaFuncAttributeMaxDynamicSharedMemorySize, FLASH_SMEM);

    // 1) kv = x @ wkv_a_w^T + b : (4096, 576)  [split-precision, raw out]
    gemm_sp<true, true, false><<<dim3(CD / 64, BS / 128, 1), 256>>>(
        D_, x, D_, 0, wkva_w, D_, 0, pkv, CD, 0, wkva_b, 1.f);

    // 2) rmsnorm latent + rope k_pe -> g_kf (tf32 out for flash)
    kv_post<<<BS, 128>>>(freqs, knw);

    // 3) q = x @ wq_w^T + b : (4096, 3072)  [raw out]
    gemm_sp<true, true, false><<<dim3(QBROW / 64, BS / 128, 1), 256>>>(
        D_, x, D_, 0, wq_w, D_, 0, pq, QBROW, 0, wq_b, 1.f);

    // 4) rope q_pe (scaled, tf32 out) -> g_qf[..., 512:576]
    q_rope<<<BS, 512>>>(freqs);

    // 5) q_absorbed per head: q_nope @ wkv_b_nope (K,N), scaled, tf32 out for flash
    gemm_sp<false, false, true><<<dim3(RK / 64, BS / 128, H_), 256>>>(
        NOPE_, pq, QBROW, QK_HD,
        wkvb, RK, (long)(NOPE_ + V_HD) * RK,
        pqf, QROW, CD, nullptr, SCALE_);

    // 6) causal flash MQA -> g_ol (raw fp32)
    flash_tc<<<dim3(S_ / 4, B_), 256, FLASH_SMEM>>>();

    // 7) per-head V up-projection: o_lat @ wkv_b_v^T -> g_ov (raw)
    gemm_sp<true, false, false><<<dim3(V_HD / 64, BS / 128, H_), 256>>>(
        RK, pol, OLROW, RK,
        wkvb + (long)NOPE_ * RK, RK, (long)(NOPE_ + V_HD) * RK,
        pov, OVROW, V_HD, nullptr, 1.f);

    // 8) final: g_ov @ wo_w^T + wo_b -> out (fp32)
    gemm_sp<true, true, false><<<dim3(D_ / 64, BS / 128, 1), 256>>>(
        OVROW, pov, OVROW, 0, wo_w, D_, 0, out, D_, 0, wo_b, 1.f);
}